// round 3
// baseline (speedup 1.0000x reference)
#include <cuda_runtime.h>
#include <cuda_bf16.h>

// DistortionLoss: B rays x N=128 samples.
// loss = 0.01 * mean_over_rays( (1/3)*sum s*w^2 + 2*sum_i [ wm_i*Wexcl_i - w_i*WMexcl_i ] )
// One warp per ray (grid-stride); lane holds 4 consecutive elements (float4 loads).
// Warp-scan gives exclusive prefix sums of w and w*m.
// Single kernel: last block (elected via atomic counter) reduces all block
// partials in a FIXED order (deterministic) and writes the scalar.

#define RAY_N 128
#define WARPS_PER_BLOCK 8
#define BLOCK_THREADS (WARPS_PER_BLOCK * 32)
#define GRID_BLOCKS 4096

__device__ float        g_partials[GRID_BLOCKS];
__device__ unsigned int g_count = 0;

__global__ void __launch_bounds__(BLOCK_THREADS)
distloss_kernel(const float* __restrict__ W,
                const float* __restrict__ M,
                const float* __restrict__ S,
                float* __restrict__ out,
                int B, double scale)
{
    const int lane = threadIdx.x & 31;
    const int wid  = threadIdx.x >> 5;
    const int warp_global = blockIdx.x * WARPS_PER_BLOCK + wid;
    const int warp_stride = gridDim.x * WARPS_PER_BLOCK;

    float acc = 0.0f;

    for (int ray = warp_global; ray < B; ray += warp_stride) {
        const size_t base = (size_t)ray * RAY_N;
        // lane covers elements [4*lane, 4*lane+4)
        const float4 w4 = __ldg(reinterpret_cast<const float4*>(W + base) + lane);
        const float4 m4 = __ldg(reinterpret_cast<const float4*>(M + base) + lane);
        const float4 s4 = __ldg(reinterpret_cast<const float4*>(S + base) + lane);

        float w[4]  = {w4.x, w4.y, w4.z, w4.w};
        float m[4]  = {m4.x, m4.y, m4.z, m4.w};
        float s[4]  = {s4.x, s4.y, s4.z, s4.w};
        float wm[4];
#pragma unroll
        for (int j = 0; j < 4; j++) wm[j] = w[j] * m[j];

        const float sw  = (w[0]  + w[1])  + (w[2]  + w[3]);
        const float swm = (wm[0] + wm[1]) + (wm[2] + wm[3]);

        // Warp inclusive scan of lane sums (w and wm together).
        float iw = sw, iwm = swm;
#pragma unroll
        for (int d = 1; d < 32; d <<= 1) {
            float tw  = __shfl_up_sync(0xffffffffu, iw,  d);
            float twm = __shfl_up_sync(0xffffffffu, iwm, d);
            if (lane >= d) { iw += tw; iwm += twm; }
        }
        // Exclusive prefixes at the start of this lane's 4 elements.
        float cw  = iw  - sw;
        float cwm = iwm - swm;

        float uni = 0.0f, bi = 0.0f;
#pragma unroll
        for (int j = 0; j < 4; j++) {
            uni = fmaf(s[j] * w[j], w[j], uni);
            bi  = fmaf(wm[j], cw, bi);
            bi  = fmaf(-w[j], cwm, bi);
            cw  += w[j];
            cwm += wm[j];
        }
        acc += (1.0f / 3.0f) * uni + 2.0f * bi;
    }

    // Intra-warp reduce.
#pragma unroll
    for (int d = 16; d; d >>= 1)
        acc += __shfl_xor_sync(0xffffffffu, acc, d);

    __shared__ float sh[WARPS_PER_BLOCK];
    __shared__ bool  s_is_last;
    if (lane == 0) sh[wid] = acc;
    __syncthreads();

    if (threadIdx.x == 0) {
        float t = 0.0f;
#pragma unroll
        for (int i = 0; i < WARPS_PER_BLOCK; i++) t += sh[i];
        g_partials[blockIdx.x] = t;
        __threadfence();
        unsigned int prev = atomicAdd(&g_count, 1u);
        s_is_last = (prev == gridDim.x - 1u);
    }
    __syncthreads();

    // Last block: deterministic final reduction in double precision.
    if (s_is_last) {
        const int n = gridDim.x;
        double dacc = 0.0;
        for (int i = threadIdx.x; i < n; i += BLOCK_THREADS)
            dacc += (double)g_partials[i];
#pragma unroll
        for (int d = 16; d; d >>= 1)
            dacc += __shfl_xor_sync(0xffffffffu, dacc, d);

        __shared__ double dsh[WARPS_PER_BLOCK];
        if (lane == 0) dsh[wid] = dacc;
        __syncthreads();
        if (threadIdx.x == 0) {
            double t = 0.0;
#pragma unroll
            for (int i = 0; i < WARPS_PER_BLOCK; i++) t += dsh[i];
            *out = (float)(t * scale);
            g_count = 0;  // reset for next launch / graph replay
        }
    }
}

extern "C" void kernel_launch(void* const* d_in, const int* in_sizes, int n_in,
                              void* d_out, int out_size)
{
    const float* W = (const float*)d_in[0];  // weights  [B, 128]
    const float* M = (const float*)d_in[1];  // distances[B, 128]
    const float* S = (const float*)d_in[2];  // intervals[B, 128]
    float* out = (float*)d_out;

    const int total = in_sizes[0];
    const int B = total / RAY_N;

    int nblocks = (B + WARPS_PER_BLOCK - 1) / WARPS_PER_BLOCK;
    if (nblocks > GRID_BLOCKS) nblocks = GRID_BLOCKS;
    if (nblocks < 1) nblocks = 1;

    const double scale = 0.01 / (double)B;  // LOSS_WEIGHT / B

    distloss_kernel<<<nblocks, BLOCK_THREADS>>>(W, M, S, out, B, scale);
}